// round 5
// baseline (speedup 1.0000x reference)
#include <cuda_runtime.h>
#include <math.h>

#define NB 512
#define FDIM 4096
#define DEG 3
#define ROWS_PER_CTA 8
#define NTHREADS 512
#define BATCH 8192
#define PSTRIDE 4608   // per-degree perm stride (elements, worst case 4096+512 pads)

// CSR of inverted hash tables (built once per launch, deterministic).
// perm entry (u16): feature(13 bits, 4096 = zero-pad slot) | sign<<15 (1 -> +x)
// g_off: per-bucket start offsets in u32 units (lists padded to even length)
__device__ __align__(16) unsigned short g_perm[DEG * PSTRIDE];
__device__ __align__(16) unsigned short g_off[DEG * (NB + 1)];

// ---------------------------------------------------------------------------
// Prologue: invert hash tables into per-bucket CSR, parallel + deterministic.
// 12 warp-tasks = (degree, quarter). Stable order: quarter-major, then
// feature order within each warp chunk via __match_any ranking.
// ---------------------------------------------------------------------------
__global__ void __launch_bounds__(NTHREADS)
build_csr(const int* __restrict__ idxh, const int* __restrict__ bith)
{
    __shared__ int hist[12][NB];      // per (deg,quarter) histogram -> cursors
    __shared__ int pc[NB];
    __shared__ int sc[2][NB];
    __shared__ int ebase[DEG][NB];    // exclusive element offsets
    const int t = threadIdx.x;
    const int w = t >> 5, lane = t & 31;

    for (int i = t; i < 12 * NB; i += NTHREADS) ((int*)hist)[i] = 0;
    __syncthreads();

    if (w < 12) {
        const int d = w >> 2, q = w & 3;
        const int base = d * FDIM + q * 1024;
        for (int it = 0; it < 32; it++) {
            int b = idxh[base + it * 32 + lane];
            atomicAdd(&hist[w][b], 1);
        }
    }
    __syncthreads();

    // pre-fill perm with pad entries (f=4096 -> reads zero slot, sign 0)
    for (int i = t; i < DEG * PSTRIDE; i += NTHREADS) g_perm[i] = 0x1000;

    for (int d = 0; d < DEG; d++) {
        int c = hist[d * 4 + 0][t] + hist[d * 4 + 1][t] +
                hist[d * 4 + 2][t] + hist[d * 4 + 3][t];
        pc[t] = c + (c & 1);                    // pad to even
        __syncthreads();
        int* s = sc[0]; int* dd = sc[1];
        s[t] = pc[t]; __syncthreads();
        for (int off = 1; off < NB; off <<= 1) {
            int v = s[t];
            if (t >= off) v += s[t - off];
            dd[t] = v;
            int* tmp = s; s = dd; dd = tmp;
            __syncthreads();
        }
        int excl = (t == 0) ? 0 : s[t - 1];
        ebase[d][t] = excl;
        g_off[d * (NB + 1) + t] = (unsigned short)(excl >> 1);
        if (t == NB - 1) g_off[d * (NB + 1) + NB] = (unsigned short)(s[NB - 1] >> 1);
        __syncthreads();
    }

    // convert histograms into per-(deg,quarter) element write cursors
    {
        for (int d = 0; d < DEG; d++) {
            int base = ebase[d][t];
            for (int q = 0; q < 4; q++) {
                int tmp = hist[d * 4 + q][t];
                hist[d * 4 + q][t] = base;
                base += tmp;
            }
        }
    }
    __syncthreads();

    if (w < 12) {
        const int d = w >> 2, q = w & 3;
        const int fbase = q * 1024;
        for (int it = 0; it < 32; it++) {
            int f  = fbase + it * 32 + lane;
            int b  = idxh[d * FDIM + f];
            int sg = bith[d * FDIM + f];
            unsigned m = __match_any_sync(0xffffffffu, b);
            int rank = __popc(m & ((1u << lane) - 1));
            int grp  = __popc(m);
            int base = hist[w][b];
            g_perm[d * PSTRIDE + base + rank] = (unsigned short)(f | (sg << 15));
            if (rank == grp - 1) hist[w][b] = base + grp;
            __syncwarp();
        }
    }
}

// ---------------------------------------------------------------------------
// Main kernel. Rows processed in pairs (r0,r1):
//  - X staged interleaved as float2 -> one LDS.64 feeds both rows
//  - gather count-sketch (no atomics), 3 degrees, both rows at once
//  - forward: 3 packed FFT-512, pack = s_d(r0) + i*s_d(r1) (1.5 waves)
//  - Hermitian split + spectral product -> P per row (k<=256)
//  - per 4 rows: packed inverse wave (2 FFT-512)
// ---------------------------------------------------------------------------
#define OFF_PERM   0          // 27648 (3*4608 u16)
#define OFF_OFF    27648      // 3078 -> pad to 3080
#define OFF_X2     30728      // 4097 float2 = 32776
#define OFF_REA    63504      // [2][512] f32 = 4096
#define OFF_IMA    67600
#define OFF_REB    71696
#define OFF_IMB    75792
#define OFF_S2     79888      // 1024 f32 (deg-2 pair stash: [re512|im512])
#define OFF_T      83984      // Tre[2][257], Tim[2][257] = 4112
#define OFF_P      88096      // Pre[4][257], Pim[4][257] = 8224
#define OFF_W      96320      // Wre[256], Wim[256] = 2048
#define SMEM_BYTES 98368

__device__ __forceinline__ void fft_stage(const float* __restrict__ xr,
                                          const float* __restrict__ xi,
                                          float* __restrict__ yr,
                                          float* __restrict__ yi,
                                          int i, int st,
                                          const float* __restrict__ Wre,
                                          const float* __restrict__ Wim)
{
    const int s = 1 << st;
    const int widx = i & ~(s - 1);
    const float wr = Wre[widx], wi = Wim[widx];
    const float ar = xr[i],       ai = xi[i];
    const float br = xr[i + 256], bi = xi[i + 256];
    const int a0 = i + widx;
    const float dr = ar - br, di = ai - bi;
    yr[a0]     = ar + br;
    yi[a0]     = ai + bi;
    yr[a0 + s] = dr * wr - di * wi;
    yi[a0 + s] = dr * wi + di * wr;
}

__global__ void __launch_bounds__(NTHREADS, 2)
poly_sketch_kernel(const float* __restrict__ X, float* __restrict__ out)
{
    extern __shared__ char sm[];
    unsigned short* shPerm = (unsigned short*)(sm + OFF_PERM);
    unsigned short* shOff  = (unsigned short*)(sm + OFF_OFF);
    float2* shX2 = (float2*)(sm + OFF_X2);
    float* reA = (float*)(sm + OFF_REA);
    float* imA = (float*)(sm + OFF_IMA);
    float* reB = (float*)(sm + OFF_REB);
    float* imB = (float*)(sm + OFF_IMB);
    float* S2  = (float*)(sm + OFF_S2);
    float* Tre = (float*)(sm + OFF_T);            // [2][257]
    float* Tim = Tre + 2 * 257;
    float* Pre = (float*)(sm + OFF_P);            // [4][257]
    float* Pim = Pre + 4 * 257;
    float* Wre = (float*)(sm + OFF_W);
    float* Wim = Wre + 256;

    const int tid = threadIdx.x;

    // ---- load CSR (int loads) + twiddles ----
    {
        const int* gp = (const int*)g_perm;
        int* sp = (int*)shPerm;
        #pragma unroll
        for (int i = tid; i < DEG * PSTRIDE / 2; i += NTHREADS)
            sp[i] = gp[i];
        for (int i = tid; i < DEG * (NB + 1); i += NTHREADS)
            shOff[i] = g_off[i];
    }
    if (tid < 256) {
        float ang = -6.283185307179586f * (float)tid * (1.0f / 512.0f);
        float s, c; sincosf(ang, &s, &c);
        Wre[tid] = c; Wim[tid] = s;
    }
    if (tid == 0) shX2[4096] = make_float2(0.f, 0.f);   // pad-entry zero slot
    __syncthreads();

    const int row0 = blockIdx.x * ROWS_PER_CTA;

    for (int g = 0; g < ROWS_PER_CTA / 4; g++) {
        const int grow = row0 + g * 4;

        for (int p = 0; p < 2; p++) {
            const int r0 = grow + 2 * p;
            const int r1 = r0 + 1;

            // ---- stage X pair, interleaved float2 ----
            {
                const float2* X0 = (const float2*)(X + (size_t)r0 * FDIM);
                const float2* X1 = (const float2*)(X + (size_t)r1 * FDIM);
                #pragma unroll
                for (int j = 0; j < (FDIM / 2) / NTHREADS; j++) {
                    int f2 = j * NTHREADS + tid;
                    float2 v0 = X0[f2];
                    float2 v1 = X1[f2];
                    shX2[2 * f2]     = make_float2(v0.x, v1.x);
                    shX2[2 * f2 + 1] = make_float2(v0.y, v1.y);
                }
            }
            __syncthreads();

            // ---- gather count-sketch, both rows, 3 degrees ----
            {
                #pragma unroll
                for (int d = 0; d < DEG; d++) {
                    const unsigned* pm = (const unsigned*)shPerm + d * (PSTRIDE / 2);
                    int s = shOff[d * (NB + 1) + tid];
                    int e = shOff[d * (NB + 1) + tid + 1];
                    float a0 = 0.f, a1 = 0.f;
                    for (int q = s; q < e; q++) {
                        unsigned w = pm[q];
                        unsigned e0 = w & 0xffffu, e1 = w >> 16;
                        float2 x0 = shX2[e0 & 0x1fffu];
                        unsigned m0 = ((~e0) & 0x8000u) << 16;
                        a0 += __int_as_float(__float_as_int(x0.x) ^ m0);
                        a1 += __int_as_float(__float_as_int(x0.y) ^ m0);
                        float2 x1 = shX2[e1 & 0x1fffu];
                        unsigned m1 = ((~e1) & 0x8000u) << 16;
                        a0 += __int_as_float(__float_as_int(x1.x) ^ m1);
                        a1 += __int_as_float(__float_as_int(x1.y) ^ m1);
                    }
                    if (d == 0)      { reA[tid] = a0; imA[tid] = a1; }
                    else if (d == 1) { reB[tid] = a0; imB[tid] = a1; }
                    else             { S2[tid] = a0;  S2[NB + tid] = a1; }
                }
            }
            __syncthreads();

            // ---- wave 1: FFT(d0 pair) on A, FFT(d1 pair) on B ----
            {
                const int i = tid & 255;
                float* sre = (tid < 256) ? reA : reB;
                float* sim = (tid < 256) ? imA : imB;
                #pragma unroll
                for (int st = 0; st < 9; st++) {
                    const int src = st & 1;
                    fft_stage(sre + src * NB, sim + src * NB,
                              sre + (src ^ 1) * NB, sim + (src ^ 1) * NB,
                              i, st, Wre, Wim);
                    __syncthreads();
                }
            }

            // ---- split + partial product T(r) = S_d0(r) * S_d1(r) ----
            if (tid <= 256) {
                const int k = tid;
                const int kr = (NB - k) & (NB - 1);
                float x = reA[NB + k],  y = imA[NB + k];
                float u = reA[NB + kr], v = imA[NB + kr];
                float a0r = 0.5f * (x + u), a0i = 0.5f * (y - v);   // S_d0(r0)
                float b0r = 0.5f * (y + v), b0i = 0.5f * (u - x);   // S_d0(r1)
                x = reB[NB + k];  y = imB[NB + k];
                u = reB[NB + kr]; v = imB[NB + kr];
                float a1r = 0.5f * (x + u), a1i = 0.5f * (y - v);   // S_d1(r0)
                float b1r = 0.5f * (y + v), b1i = 0.5f * (u - x);   // S_d1(r1)
                Tre[k]       = a0r * a1r - a0i * a1i;
                Tim[k]       = a0r * a1i + a0i * a1r;
                Tre[257 + k] = b0r * b1r - b0i * b1i;
                Tim[257 + k] = b0r * b1i + b0i * b1r;
            }
            __syncthreads();

            // ---- wave 2: FFT(d2 pair), stage0 reads S2 stash, slot A ----
            #pragma unroll
            for (int st = 0; st < 9; st++) {
                if (tid < 256) {
                    const float *xr, *xi; float *yr, *yi;
                    if (st == 0) { xr = S2; xi = S2 + NB; yr = reA + NB; yi = imA + NB; }
                    else {
                        int s = st & 1;
                        xr = reA + s * NB;        xi = imA + s * NB;
                        yr = reA + (s ^ 1) * NB;  yi = imA + (s ^ 1) * NB;
                    }
                    fft_stage(xr, xi, yr, yi, tid, st, Wre, Wim);
                }
                __syncthreads();
            }

            // ---- split d2 + final product -> P rows 2p, 2p+1 ----
            if (tid <= 256) {
                const int k = tid;
                const int kr = (NB - k) & (NB - 1);
                float x = reA[NB + k],  y = imA[NB + k];
                float u = reA[NB + kr], v = imA[NB + kr];
                float a2r = 0.5f * (x + u), a2i = 0.5f * (y - v);   // S_d2(r0)
                float b2r = 0.5f * (y + v), b2i = 0.5f * (u - x);   // S_d2(r1)
                float t0r = Tre[k], t0i = Tim[k];
                float t1r = Tre[257 + k], t1i = Tim[257 + k];
                Pre[(2 * p) * 257 + k]     = t0r * a2r - t0i * a2i;
                Pim[(2 * p) * 257 + k]     = t0r * a2i + t0i * a2r;
                Pre[(2 * p + 1) * 257 + k] = t1r * b2r - t1i * b2i;
                Pim[(2 * p + 1) * 257 + k] = t1r * b2i + t1i * b2r;
            }
            __syncthreads();
        }

        // ---- packed inverse: Q01 = conj(P0 + iP1) -> A, Q23 -> B ----
        {
            const int k = tid;
            float p0r, p0i, p1r, p1i, p2r, p2i, p3r, p3i;
            if (k <= 256) {
                p0r = Pre[k];           p0i = Pim[k];
                p1r = Pre[257 + k];     p1i = Pim[257 + k];
                p2r = Pre[2 * 257 + k]; p2i = Pim[2 * 257 + k];
                p3r = Pre[3 * 257 + k]; p3i = Pim[3 * 257 + k];
            } else {
                const int kr = NB - k;
                p0r = Pre[kr];           p0i = -Pim[kr];
                p1r = Pre[257 + kr];     p1i = -Pim[257 + kr];
                p2r = Pre[2 * 257 + kr]; p2i = -Pim[2 * 257 + kr];
                p3r = Pre[3 * 257 + kr]; p3i = -Pim[3 * 257 + kr];
            }
            reA[k] = p0r - p1i;
            imA[k] = -(p0i + p1r);
            reB[k] = p2r - p3i;
            imB[k] = -(p2i + p3r);
        }
        __syncthreads();

        {
            const int i = tid & 255;
            float* sre = (tid < 256) ? reA : reB;
            float* sim = (tid < 256) ? imA : imB;
            #pragma unroll
            for (int st = 0; st < 9; st++) {
                const int src = st & 1;
                fft_stage(sre + src * NB, sim + src * NB,
                          sre + (src ^ 1) * NB, sim + (src ^ 1) * NB,
                          i, st, Wre, Wim);
                __syncthreads();
            }
        }

        {
            const float inv = 1.0f / 512.0f;
            out[(size_t)(grow + 0) * NB + tid] =  reA[NB + tid] * inv;
            out[(size_t)(grow + 1) * NB + tid] = -imA[NB + tid] * inv;
            out[(size_t)(grow + 2) * NB + tid] =  reB[NB + tid] * inv;
            out[(size_t)(grow + 3) * NB + tid] = -imB[NB + tid] * inv;
        }
        __syncthreads();
    }
}

extern "C" void kernel_launch(void* const* d_in, const int* in_sizes, int n_in,
                              void* d_out, int out_size)
{
    const float* X  = (const float*)d_in[0];
    const int*   ih = (const int*)d_in[1];
    const int*   bh = (const int*)d_in[2];
    float* out = (float*)d_out;

    cudaFuncSetAttribute(poly_sketch_kernel,
                         cudaFuncAttributeMaxDynamicSharedMemorySize, SMEM_BYTES);
    build_csr<<<1, NTHREADS>>>(ih, bh);
    poly_sketch_kernel<<<BATCH / ROWS_PER_CTA, NTHREADS, SMEM_BYTES>>>(X, out);
}

// round 6
// speedup vs baseline: 1.0056x; 1.0056x over previous
#include <cuda_runtime.h>
#include <math.h>

#define NB 512
#define FDIM 4096
#define DEG 3
#define ROWS_PER_CTA 8
#define NTHREADS 512
#define BATCH 8192
#define PSTRIDE 4608   // per-degree perm stride (elements, worst case 4096+512 pads)

// CSR of inverted hash tables (built once per launch, deterministic).
// perm entry (u16): feature(13 bits, 4096 = zero-pad slot) | sign<<15 (1 -> +x)
// g_off: per-bucket start offsets in u32 units (lists padded to even length)
__device__ __align__(16) unsigned short g_perm[DEG * PSTRIDE];
__device__ __align__(16) unsigned short g_off[DEG * (NB + 1)];

// ---------------------------------------------------------------------------
// Prologue: invert hash tables into per-bucket CSR, parallel + deterministic.
// 12 warp-tasks = (degree, quarter). Stable order: quarter-major, then
// feature order within each warp chunk via __match_any ranking.
// ---------------------------------------------------------------------------
__global__ void __launch_bounds__(NTHREADS)
build_csr(const int* __restrict__ idxh, const int* __restrict__ bith)
{
    __shared__ int hist[12][NB];      // per (deg,quarter) histogram -> cursors
    __shared__ int pc[NB];
    __shared__ int sc[2][NB];
    __shared__ int ebase[DEG][NB];    // exclusive element offsets
    const int t = threadIdx.x;
    const int w = t >> 5, lane = t & 31;

    for (int i = t; i < 12 * NB; i += NTHREADS) ((int*)hist)[i] = 0;
    __syncthreads();

    if (w < 12) {
        const int d = w >> 2, q = w & 3;
        const int base = d * FDIM + q * 1024;
        for (int it = 0; it < 32; it++) {
            int b = idxh[base + it * 32 + lane];
            atomicAdd(&hist[w][b], 1);
        }
    }
    __syncthreads();

    // pre-fill perm with pad entries (f=4096 -> reads zero slot, sign 0)
    for (int i = t; i < DEG * PSTRIDE; i += NTHREADS) g_perm[i] = 0x1000;

    for (int d = 0; d < DEG; d++) {
        int c = hist[d * 4 + 0][t] + hist[d * 4 + 1][t] +
                hist[d * 4 + 2][t] + hist[d * 4 + 3][t];
        pc[t] = c + (c & 1);                    // pad to even
        __syncthreads();
        int* s = sc[0]; int* dd = sc[1];
        s[t] = pc[t]; __syncthreads();
        for (int off = 1; off < NB; off <<= 1) {
            int v = s[t];
            if (t >= off) v += s[t - off];
            dd[t] = v;
            int* tmp = s; s = dd; dd = tmp;
            __syncthreads();
        }
        int excl = (t == 0) ? 0 : s[t - 1];
        ebase[d][t] = excl;
        g_off[d * (NB + 1) + t] = (unsigned short)(excl >> 1);
        if (t == NB - 1) g_off[d * (NB + 1) + NB] = (unsigned short)(s[NB - 1] >> 1);
        __syncthreads();
    }

    // convert histograms into per-(deg,quarter) element write cursors
    {
        for (int d = 0; d < DEG; d++) {
            int base = ebase[d][t];
            for (int q = 0; q < 4; q++) {
                int tmp = hist[d * 4 + q][t];
                hist[d * 4 + q][t] = base;
                base += tmp;
            }
        }
    }
    __syncthreads();

    if (w < 12) {
        const int d = w >> 2, q = w & 3;
        const int fbase = q * 1024;
        for (int it = 0; it < 32; it++) {
            int f  = fbase + it * 32 + lane;
            int b  = idxh[d * FDIM + f];
            int sg = bith[d * FDIM + f];
            unsigned m = __match_any_sync(0xffffffffu, b);
            int rank = __popc(m & ((1u << lane) - 1));
            int grp  = __popc(m);
            int base = hist[w][b];
            g_perm[d * PSTRIDE + base + rank] = (unsigned short)(f | (sg << 15));
            if (rank == grp - 1) hist[w][b] = base + grp;
            __syncwarp();
        }
    }
}

// ---------------------------------------------------------------------------
// Main kernel. Rows processed in pairs (r0,r1):
//  - X staged interleaved as float2 -> one LDS.64 feeds both rows
//  - gather count-sketch (no atomics), 3 degrees, both rows at once
//  - forward: 3 packed FFT-512, pack = s_d(r0) + i*s_d(r1) (1.5 waves)
//  - Hermitian split + spectral product -> P per row (k<=256)
//  - per 4 rows: packed inverse wave (2 FFT-512)
// ---------------------------------------------------------------------------
#define OFF_PERM   0          // 27648 (3*4608 u16)
#define OFF_OFF    27648      // 3078 -> pad to 3080
#define OFF_X2     30728      // 4097 float2 = 32776
#define OFF_REA    63504      // [2][512] f32 = 4096
#define OFF_IMA    67600
#define OFF_REB    71696
#define OFF_IMB    75792
#define OFF_S2     79888      // 1024 f32 (deg-2 pair stash: [re512|im512])
#define OFF_T      83984      // Tre[2][257], Tim[2][257] = 4112
#define OFF_P      88096      // Pre[4][257], Pim[4][257] = 8224
#define OFF_W      96320      // Wre[256], Wim[256] = 2048
#define SMEM_BYTES 98368

__device__ __forceinline__ void fft_stage(const float* __restrict__ xr,
                                          const float* __restrict__ xi,
                                          float* __restrict__ yr,
                                          float* __restrict__ yi,
                                          int i, int st,
                                          const float* __restrict__ Wre,
                                          const float* __restrict__ Wim)
{
    const int s = 1 << st;
    const int widx = i & ~(s - 1);
    const float wr = Wre[widx], wi = Wim[widx];
    const float ar = xr[i],       ai = xi[i];
    const float br = xr[i + 256], bi = xi[i + 256];
    const int a0 = i + widx;
    const float dr = ar - br, di = ai - bi;
    yr[a0]     = ar + br;
    yi[a0]     = ai + bi;
    yr[a0 + s] = dr * wr - di * wi;
    yi[a0 + s] = dr * wi + di * wr;
}

__global__ void __launch_bounds__(NTHREADS, 2)
poly_sketch_kernel(const float* __restrict__ X, float* __restrict__ out)
{
    extern __shared__ char sm[];
    unsigned short* shPerm = (unsigned short*)(sm + OFF_PERM);
    unsigned short* shOff  = (unsigned short*)(sm + OFF_OFF);
    float2* shX2 = (float2*)(sm + OFF_X2);
    float* reA = (float*)(sm + OFF_REA);
    float* imA = (float*)(sm + OFF_IMA);
    float* reB = (float*)(sm + OFF_REB);
    float* imB = (float*)(sm + OFF_IMB);
    float* S2  = (float*)(sm + OFF_S2);
    float* Tre = (float*)(sm + OFF_T);            // [2][257]
    float* Tim = Tre + 2 * 257;
    float* Pre = (float*)(sm + OFF_P);            // [4][257]
    float* Pim = Pre + 4 * 257;
    float* Wre = (float*)(sm + OFF_W);
    float* Wim = Wre + 256;

    const int tid = threadIdx.x;

    // ---- load CSR (int loads) + twiddles ----
    {
        const int* gp = (const int*)g_perm;
        int* sp = (int*)shPerm;
        #pragma unroll
        for (int i = tid; i < DEG * PSTRIDE / 2; i += NTHREADS)
            sp[i] = gp[i];
        for (int i = tid; i < DEG * (NB + 1); i += NTHREADS)
            shOff[i] = g_off[i];
    }
    if (tid < 256) {
        float ang = -6.283185307179586f * (float)tid * (1.0f / 512.0f);
        float s, c; sincosf(ang, &s, &c);
        Wre[tid] = c; Wim[tid] = s;
    }
    if (tid == 0) shX2[4096] = make_float2(0.f, 0.f);   // pad-entry zero slot
    __syncthreads();

    const int row0 = blockIdx.x * ROWS_PER_CTA;

    for (int g = 0; g < ROWS_PER_CTA / 4; g++) {
        const int grow = row0 + g * 4;

        for (int p = 0; p < 2; p++) {
            const int r0 = grow + 2 * p;
            const int r1 = r0 + 1;

            // ---- stage X pair, interleaved float2 ----
            {
                const float2* X0 = (const float2*)(X + (size_t)r0 * FDIM);
                const float2* X1 = (const float2*)(X + (size_t)r1 * FDIM);
                #pragma unroll
                for (int j = 0; j < (FDIM / 2) / NTHREADS; j++) {
                    int f2 = j * NTHREADS + tid;
                    float2 v0 = X0[f2];
                    float2 v1 = X1[f2];
                    shX2[2 * f2]     = make_float2(v0.x, v1.x);
                    shX2[2 * f2 + 1] = make_float2(v0.y, v1.y);
                }
            }
            __syncthreads();

            // ---- gather count-sketch, both rows, 3 degrees ----
            {
                #pragma unroll
                for (int d = 0; d < DEG; d++) {
                    const unsigned* pm = (const unsigned*)shPerm + d * (PSTRIDE / 2);
                    int s = shOff[d * (NB + 1) + tid];
                    int e = shOff[d * (NB + 1) + tid + 1];
                    float a0 = 0.f, a1 = 0.f;
                    for (int q = s; q < e; q++) {
                        unsigned w = pm[q];
                        unsigned e0 = w & 0xffffu, e1 = w >> 16;
                        float2 x0 = shX2[e0 & 0x1fffu];
                        unsigned m0 = ((~e0) & 0x8000u) << 16;
                        a0 += __int_as_float(__float_as_int(x0.x) ^ m0);
                        a1 += __int_as_float(__float_as_int(x0.y) ^ m0);
                        float2 x1 = shX2[e1 & 0x1fffu];
                        unsigned m1 = ((~e1) & 0x8000u) << 16;
                        a0 += __int_as_float(__float_as_int(x1.x) ^ m1);
                        a1 += __int_as_float(__float_as_int(x1.y) ^ m1);
                    }
                    if (d == 0)      { reA[tid] = a0; imA[tid] = a1; }
                    else if (d == 1) { reB[tid] = a0; imB[tid] = a1; }
                    else             { S2[tid] = a0;  S2[NB + tid] = a1; }
                }
            }
            __syncthreads();

            // ---- wave 1: FFT(d0 pair) on A, FFT(d1 pair) on B ----
            {
                const int i = tid & 255;
                float* sre = (tid < 256) ? reA : reB;
                float* sim = (tid < 256) ? imA : imB;
                #pragma unroll
                for (int st = 0; st < 9; st++) {
                    const int src = st & 1;
                    fft_stage(sre + src * NB, sim + src * NB,
                              sre + (src ^ 1) * NB, sim + (src ^ 1) * NB,
                              i, st, Wre, Wim);
                    __syncthreads();
                }
            }

            // ---- split + partial product T(r) = S_d0(r) * S_d1(r) ----
            if (tid <= 256) {
                const int k = tid;
                const int kr = (NB - k) & (NB - 1);
                float x = reA[NB + k],  y = imA[NB + k];
                float u = reA[NB + kr], v = imA[NB + kr];
                float a0r = 0.5f * (x + u), a0i = 0.5f * (y - v);   // S_d0(r0)
                float b0r = 0.5f * (y + v), b0i = 0.5f * (u - x);   // S_d0(r1)
                x = reB[NB + k];  y = imB[NB + k];
                u = reB[NB + kr]; v = imB[NB + kr];
                float a1r = 0.5f * (x + u), a1i = 0.5f * (y - v);   // S_d1(r0)
                float b1r = 0.5f * (y + v), b1i = 0.5f * (u - x);   // S_d1(r1)
                Tre[k]       = a0r * a1r - a0i * a1i;
                Tim[k]       = a0r * a1i + a0i * a1r;
                Tre[257 + k] = b0r * b1r - b0i * b1i;
                Tim[257 + k] = b0r * b1i + b0i * b1r;
            }
            __syncthreads();

            // ---- wave 2: FFT(d2 pair), stage0 reads S2 stash, slot A ----
            #pragma unroll
            for (int st = 0; st < 9; st++) {
                if (tid < 256) {
                    const float *xr, *xi; float *yr, *yi;
                    if (st == 0) { xr = S2; xi = S2 + NB; yr = reA + NB; yi = imA + NB; }
                    else {
                        int s = st & 1;
                        xr = reA + s * NB;        xi = imA + s * NB;
                        yr = reA + (s ^ 1) * NB;  yi = imA + (s ^ 1) * NB;
                    }
                    fft_stage(xr, xi, yr, yi, tid, st, Wre, Wim);
                }
                __syncthreads();
            }

            // ---- split d2 + final product -> P rows 2p, 2p+1 ----
            if (tid <= 256) {
                const int k = tid;
                const int kr = (NB - k) & (NB - 1);
                float x = reA[NB + k],  y = imA[NB + k];
                float u = reA[NB + kr], v = imA[NB + kr];
                float a2r = 0.5f * (x + u), a2i = 0.5f * (y - v);   // S_d2(r0)
                float b2r = 0.5f * (y + v), b2i = 0.5f * (u - x);   // S_d2(r1)
                float t0r = Tre[k], t0i = Tim[k];
                float t1r = Tre[257 + k], t1i = Tim[257 + k];
                Pre[(2 * p) * 257 + k]     = t0r * a2r - t0i * a2i;
                Pim[(2 * p) * 257 + k]     = t0r * a2i + t0i * a2r;
                Pre[(2 * p + 1) * 257 + k] = t1r * b2r - t1i * b2i;
                Pim[(2 * p + 1) * 257 + k] = t1r * b2i + t1i * b2r;
            }
            __syncthreads();
        }

        // ---- packed inverse: Q01 = conj(P0 + iP1) -> A, Q23 -> B ----
        {
            const int k = tid;
            float p0r, p0i, p1r, p1i, p2r, p2i, p3r, p3i;
            if (k <= 256) {
                p0r = Pre[k];           p0i = Pim[k];
                p1r = Pre[257 + k];     p1i = Pim[257 + k];
                p2r = Pre[2 * 257 + k]; p2i = Pim[2 * 257 + k];
                p3r = Pre[3 * 257 + k]; p3i = Pim[3 * 257 + k];
            } else {
                const int kr = NB - k;
                p0r = Pre[kr];           p0i = -Pim[kr];
                p1r = Pre[257 + kr];     p1i = -Pim[257 + kr];
                p2r = Pre[2 * 257 + kr]; p2i = -Pim[2 * 257 + kr];
                p3r = Pre[3 * 257 + kr]; p3i = -Pim[3 * 257 + kr];
            }
            reA[k] = p0r - p1i;
            imA[k] = -(p0i + p1r);
            reB[k] = p2r - p3i;
            imB[k] = -(p2i + p3r);
        }
        __syncthreads();

        {
            const int i = tid & 255;
            float* sre = (tid < 256) ? reA : reB;
            float* sim = (tid < 256) ? imA : imB;
            #pragma unroll
            for (int st = 0; st < 9; st++) {
                const int src = st & 1;
                fft_stage(sre + src * NB, sim + src * NB,
                          sre + (src ^ 1) * NB, sim + (src ^ 1) * NB,
                          i, st, Wre, Wim);
                __syncthreads();
            }
        }

        {
            const float inv = 1.0f / 512.0f;
            out[(size_t)(grow + 0) * NB + tid] =  reA[NB + tid] * inv;
            out[(size_t)(grow + 1) * NB + tid] = -imA[NB + tid] * inv;
            out[(size_t)(grow + 2) * NB + tid] =  reB[NB + tid] * inv;
            out[(size_t)(grow + 3) * NB + tid] = -imB[NB + tid] * inv;
        }
        __syncthreads();
    }
}

extern "C" void kernel_launch(void* const* d_in, const int* in_sizes, int n_in,
                              void* d_out, int out_size)
{
    const float* X  = (const float*)d_in[0];
    const int*   ih = (const int*)d_in[1];
    const int*   bh = (const int*)d_in[2];
    float* out = (float*)d_out;

    cudaFuncSetAttribute(poly_sketch_kernel,
                         cudaFuncAttributeMaxDynamicSharedMemorySize, SMEM_BYTES);
    build_csr<<<1, NTHREADS>>>(ih, bh);
    poly_sketch_kernel<<<BATCH / ROWS_PER_CTA, NTHREADS, SMEM_BYTES>>>(X, out);
}